// round 1
// baseline (speedup 1.0000x reference)
#include <cuda_runtime.h>
#include <math.h>
#include <stdint.h>

// Problem constants
#define BB   2
#define SS   2048
#define HH   2048
#define NHH  16
#define HDD  128
#define H3   6144          // 3*H
#define BSR  4096          // B*S rows
#define ALPHA 0.08838834764831845f  // 1/sqrt(128)

// Scratch (static __device__ arrays: allowed; no allocations anywhere)
__device__ float g_qkv[(size_t)BSR * H3];   // [B*S, 3H]  ~100.7 MB
__device__ float g_ctx[(size_t)BSR * HH];   // [B*S, H]   ~33.5 MB

// ---------------------------------------------------------------------------
// Packed fp32x2 helpers (Blackwell FFMA2 path: 2x fp32 FMA throughput)
// ---------------------------------------------------------------------------
__device__ __forceinline__ unsigned long long pack2(float x, float y) {
    unsigned long long r;
    asm("mov.b64 %0, {%1, %2};" : "=l"(r) : "f"(x), "f"(y));
    return r;
}
__device__ __forceinline__ void unpack2(unsigned long long v, float& x, float& y) {
    asm("mov.b64 {%0, %1}, %2;" : "=f"(x), "=f"(y) : "l"(v));
}
__device__ __forceinline__ unsigned long long ffma2(unsigned long long a,
                                                    unsigned long long b,
                                                    unsigned long long c) {
    unsigned long long d;
    asm("fma.rn.f32x2 %0, %1, %2, %3;" : "=l"(d) : "l"(a), "l"(b), "l"(c));
    return d;
}

// ---------------------------------------------------------------------------
// Tiled fp32 GEMM: C[M,N] = A[M,K] @ W[K,N] + bias[N] (+ resid[M,N] if EPI==1)
// BM=BN=128, BK=16, 256 threads, 8x8 per thread, FFMA2 inner loop.
// All dims divide tile sizes exactly for this problem (no bounds checks).
// ---------------------------------------------------------------------------
#define GBM 128
#define GBN 128
#define GBK 16

template <int EPI>
__global__ __launch_bounds__(256)
void gemm_epi(const float* __restrict__ A, const float* __restrict__ W,
              const float* __restrict__ bias, const float* __restrict__ resid,
              float* __restrict__ C, int M, int N, int K) {
    __shared__ float As[GBK][GBM];   // transposed A tile
    __shared__ float Bs[GBK][GBN];

    const int tid = threadIdx.x;
    const int bm  = blockIdx.y * GBM;
    const int bn  = blockIdx.x * GBN;
    const int tx  = tid & 15;
    const int ty  = tid >> 4;

    // global-load indices
    const int arow = tid >> 2;             // 0..63  (+64 on second pass)
    const int acol = (tid & 3) << 2;       // 0,4,8,12
    const int brow = tid >> 5;             // 0..7   (+8 on second pass)
    const int bcol = (tid & 31) << 2;      // 0..124

    unsigned long long accp[8][4];
    #pragma unroll
    for (int i = 0; i < 8; i++)
        #pragma unroll
        for (int j = 0; j < 4; j++) accp[i][j] = 0ULL;

    for (int k0 = 0; k0 < K; k0 += GBK) {
        #pragma unroll
        for (int t = 0; t < 2; t++) {
            int r = arow + t * 64;
            float4 a = *(const float4*)(A + (size_t)(bm + r) * K + k0 + acol);
            As[acol + 0][r] = a.x;
            As[acol + 1][r] = a.y;
            As[acol + 2][r] = a.z;
            As[acol + 3][r] = a.w;
        }
        #pragma unroll
        for (int t = 0; t < 2; t++) {
            int r = brow + t * 8;
            *(float4*)(&Bs[r][bcol]) =
                *(const float4*)(W + (size_t)(k0 + r) * N + bn + bcol);
        }
        __syncthreads();

        #pragma unroll
        for (int kk = 0; kk < GBK; kk++) {
            float a[8];
            *(float4*)(a)     = *(const float4*)(&As[kk][ty * 8]);
            *(float4*)(a + 4) = *(const float4*)(&As[kk][ty * 8 + 4]);
            unsigned long long bp[4];
            const unsigned long long* bsp =
                (const unsigned long long*)(&Bs[kk][tx * 8]);
            bp[0] = bsp[0]; bp[1] = bsp[1]; bp[2] = bsp[2]; bp[3] = bsp[3];
            #pragma unroll
            for (int i = 0; i < 8; i++) {
                unsigned long long asplat = pack2(a[i], a[i]);
                #pragma unroll
                for (int jp = 0; jp < 4; jp++)
                    accp[i][jp] = ffma2(asplat, bp[jp], accp[i][jp]);
            }
        }
        __syncthreads();
    }

    // epilogue
    #pragma unroll
    for (int i = 0; i < 8; i++) {
        float acc[8];
        #pragma unroll
        for (int jp = 0; jp < 4; jp++)
            unpack2(accp[i][jp], acc[2 * jp], acc[2 * jp + 1]);

        size_t row = (size_t)(bm + ty * 8 + i);
        float* crow = C + row * N + bn + tx * 8;
        const float* rrow = resid ? (resid + row * N + bn + tx * 8) : nullptr;
        float4 o0, o1;
        float* ov = (float*)&o0;
        #pragma unroll
        for (int j = 0; j < 8; j++) {
            float v = acc[j] + bias[bn + tx * 8 + j];
            if (EPI == 1) v += rrow[j];
            if (j < 4) ((float*)&o0)[j] = v; else ((float*)&o1)[j - 4] = v;
        }
        (void)ov;
        *(float4*)(crow)     = o0;
        *(float4*)(crow + 4) = o1;
    }
}

// ---------------------------------------------------------------------------
// Flash-style causal attention with ALiBi.
// One CTA handles (bh, 64-row Q tile). 256 threads, 16x16 layout.
// Thread (ty,tx): score rows {ty+16r}, cols {tx+16c}; output cols {tx+16c}, c<8.
// Shared: Q/K/V [64][132] + P [64][68]  = 118784 B dynamic.
// ---------------------------------------------------------------------------
#define QKV_STRIDE 132
#define P_STRIDE   68
#define ATTN_SMEM  ((3 * 64 * QKV_STRIDE + 64 * P_STRIDE) * 4)

__global__ __launch_bounds__(256)
void attn_kernel(const float* __restrict__ qkv, const float* __restrict__ alibi,
                 float* __restrict__ ctx) {
    extern __shared__ float sm[];
    float* Qs = sm;
    float* Ks = sm + 64 * QKV_STRIDE;
    float* Vs = sm + 2 * 64 * QKV_STRIDE;
    float* Ps = sm + 3 * 64 * QKV_STRIDE;

    const int tid = threadIdx.x;
    const int tx  = tid & 15;
    const int ty  = tid >> 4;
    const int qt  = blockIdx.x;          // 0..31
    const int bh  = blockIdx.y;          // 0..31 = b*NH + h
    const int b   = bh >> 4;
    const int h   = bh & 15;
    const int q0  = qt * 64;

    const size_t base = (size_t)b * SS * H3 + (size_t)h * (3 * HDD);

    // load Q tile (which=1 -> +HD), premultiply by ALPHA
    #pragma unroll
    for (int t = 0; t < 8; t++) {
        int idx = tid + 256 * t;
        int r   = idx >> 5;
        int c4  = (idx & 31) << 2;
        float4 qv = *(const float4*)(qkv + base + (size_t)(q0 + r) * H3 + HDD + c4);
        qv.x *= ALPHA; qv.y *= ALPHA; qv.z *= ALPHA; qv.w *= ALPHA;
        *(float4*)(Qs + r * QKV_STRIDE + c4) = qv;
    }

    float m[4], l[4], o[4][8];
    #pragma unroll
    for (int r = 0; r < 4; r++) {
        m[r] = -INFINITY; l[r] = 0.0f;
        #pragma unroll
        for (int c = 0; c < 8; c++) o[r][c] = 0.0f;
    }

    const float* ali = alibi + (size_t)bh * SS;

    for (int kt = 0; kt <= qt; kt++) {
        const int k0 = kt * 64;
        __syncthreads();  // protect prior-iteration reads (and Q store on kt=0)
        #pragma unroll
        for (int t = 0; t < 8; t++) {
            int idx = tid + 256 * t;
            int r   = idx >> 5;
            int c4  = (idx & 31) << 2;
            size_t g = base + (size_t)(k0 + r) * H3 + c4;
            *(float4*)(Ks + r * QKV_STRIDE + c4) = *(const float4*)(qkv + g);           // key
            *(float4*)(Vs + r * QKV_STRIDE + c4) = *(const float4*)(qkv + g + 2 * HDD); // value
        }
        __syncthreads();

        // scores S = (alpha*q) . k
        float s[4][4];
        #pragma unroll
        for (int r = 0; r < 4; r++)
            #pragma unroll
            for (int c = 0; c < 4; c++) s[r][c] = 0.0f;

        #pragma unroll 4
        for (int kk = 0; kk < HDD; kk += 4) {
            float4 qv[4], kv[4];
            #pragma unroll
            for (int r = 0; r < 4; r++)
                qv[r] = *(const float4*)(Qs + (ty + 16 * r) * QKV_STRIDE + kk);
            #pragma unroll
            for (int c = 0; c < 4; c++)
                kv[c] = *(const float4*)(Ks + (tx + 16 * c) * QKV_STRIDE + kk);
            #pragma unroll
            for (int r = 0; r < 4; r++)
                #pragma unroll
                for (int c = 0; c < 4; c++)
                    s[r][c] += qv[r].x * kv[c].x + qv[r].y * kv[c].y +
                               qv[r].z * kv[c].z + qv[r].w * kv[c].w;
        }

        // alibi + causal mask (only diagonal tile can mask)
        float av[4];
        #pragma unroll
        for (int c = 0; c < 4; c++) av[c] = ali[k0 + tx + 16 * c];
        const bool diag = (kt == qt);
        #pragma unroll
        for (int r = 0; r < 4; r++) {
            int ig = q0 + ty + 16 * r;
            #pragma unroll
            for (int c = 0; c < 4; c++) {
                int jg = k0 + tx + 16 * c;
                float val = s[r][c] + av[c];
                s[r][c] = (diag && (jg > ig)) ? -INFINITY : val;
            }
        }

        // online softmax (row groups = 16 lanes sharing ty)
        #pragma unroll
        for (int r = 0; r < 4; r++) {
            float mt = fmaxf(fmaxf(s[r][0], s[r][1]), fmaxf(s[r][2], s[r][3]));
            #pragma unroll
            for (int off = 8; off >= 1; off >>= 1)
                mt = fmaxf(mt, __shfl_xor_sync(0xffffffffu, mt, off, 16));
            float mn = fmaxf(m[r], mt);
            float f  = __expf(m[r] - mn);
            float ps = 0.0f;
            #pragma unroll
            for (int c = 0; c < 4; c++) {
                float p = __expf(s[r][c] - mn);
                s[r][c] = p;
                ps += p;
            }
            #pragma unroll
            for (int off = 8; off >= 1; off >>= 1)
                ps += __shfl_xor_sync(0xffffffffu, ps, off, 16);
            l[r] = l[r] * f + ps;
            m[r] = mn;
            #pragma unroll
            for (int c = 0; c < 8; c++) o[r][c] *= f;
            #pragma unroll
            for (int c = 0; c < 4; c++)
                Ps[(ty + 16 * r) * P_STRIDE + tx + 16 * c] = s[r][c];
        }
        __syncthreads();

        // O += P @ V
        #pragma unroll 2
        for (int j = 0; j < 64; j++) {
            float pv[4], vv[8];
            #pragma unroll
            for (int r = 0; r < 4; r++) pv[r] = Ps[(ty + 16 * r) * P_STRIDE + j];
            #pragma unroll
            for (int c = 0; c < 8; c++) vv[c] = Vs[j * QKV_STRIDE + tx + 16 * c];
            #pragma unroll
            for (int r = 0; r < 4; r++)
                #pragma unroll
                for (int c = 0; c < 8; c++) o[r][c] += pv[r] * vv[c];
        }
    }

    // normalize + write merged-head ctx [B*S, H]
    #pragma unroll
    for (int r = 0; r < 4; r++) {
        float inv = 1.0f / l[r];
        int ig = q0 + ty + 16 * r;
        float* crow = ctx + ((size_t)b * SS + ig) * HH + h * HDD;
        #pragma unroll
        for (int c = 0; c < 8; c++) crow[tx + 16 * c] = o[r][c] * inv;
    }
}

// ---------------------------------------------------------------------------
// Launch
// ---------------------------------------------------------------------------
extern "C" void kernel_launch(void* const* d_in, const int* in_sizes, int n_in,
                              void* d_out, int out_size) {
    (void)in_sizes; (void)n_in; (void)out_size;
    const float* hs    = (const float*)d_in[0];
    // d_in[1] = attention_mask (deterministic causal triu; applied analytically)
    const float* resid = (const float*)d_in[2];
    const float* alibi = (const float*)d_in[3];
    const float* Wqkv  = (const float*)d_in[4];
    const float* bqkv  = (const float*)d_in[5];
    const float* Wd    = (const float*)d_in[6];
    const float* bd    = (const float*)d_in[7];
    float* out = (float*)d_out;

    float* qkvp = nullptr;
    float* ctxp = nullptr;
    cudaGetSymbolAddress((void**)&qkvp, g_qkv);
    cudaGetSymbolAddress((void**)&ctxp, g_ctx);

    cudaFuncSetAttribute(attn_kernel,
                         cudaFuncAttributeMaxDynamicSharedMemorySize, ATTN_SMEM);

    // 1) qkv = hidden @ Wqkv + bqkv
    dim3 g1(H3 / GBN, BSR / GBM);  // (48, 32)
    gemm_epi<0><<<g1, 256>>>(hs, Wqkv, bqkv, nullptr, qkvp, BSR, H3, HH);

    // 2) ctx = softmax(alibi + alpha*q k^T, causal) @ v   (merged heads)
    dim3 ga(SS / 64, BB * NHH);    // (32, 32)
    attn_kernel<<<ga, 256, ATTN_SMEM>>>(qkvp, alibi, ctxp);

    // 3) out = ctx @ Wd + bd + residual
    dim3 g2(HH / GBN, BSR / GBM);  // (16, 32)
    gemm_epi<1><<<g2, 256>>>(ctxp, Wd, bd, resid, out, BSR, HH, HH);
}

// round 3
// speedup vs baseline: 1.4981x; 1.4981x over previous
#include <cuda_runtime.h>
#include <math.h>
#include <stdint.h>
#include <mma.h>

using namespace nvcuda;

// Problem constants
#define BB   2
#define SS   2048
#define HH   2048
#define NHH  16
#define HDD  128
#define H3   6144
#define BSR  4096
#define ALPHA 0.08838834764831845f

// Scratch
__device__ float g_qkv[(size_t)BSR * H3];
__device__ float g_ctx[(size_t)BSR * HH];
__device__ float g_wqkvt[(size_t)H3 * HH];  // Wqkv^T [6144][2048], tf32-rounded
__device__ float g_wdt[(size_t)HH * HH];    // Wd^T   [2048][2048], tf32-rounded

// ---------------------------------------------------------------------------
// Helpers
// ---------------------------------------------------------------------------
__device__ __forceinline__ uint32_t smem_u32(const void* p) {
    uint32_t a;
    asm("{ .reg .u64 t; cvta.to.shared.u64 t, %1; cvt.u32.u64 %0, t; }" : "=r"(a) : "l"(p));
    return a;
}
__device__ __forceinline__ void cp16(uint32_t dst, const void* src) {
    asm volatile("cp.async.cg.shared.global [%0], [%1], 16;" :: "r"(dst), "l"(src));
}
__device__ __forceinline__ float to_tf32(float x) {
    uint32_t u;
    asm("cvt.rna.tf32.f32 %0, %1;" : "=r"(u) : "f"(x));
    return __uint_as_float(u);
}

// ---------------------------------------------------------------------------
// Transpose + round to tf32: Wt[n][k] = rna_tf32(W[k][n]).  W is [K][N].
// ---------------------------------------------------------------------------
__global__ __launch_bounds__(256)
void transpose_tf32(const float* __restrict__ W, float* __restrict__ Wt,
                    int K, int N) {
    __shared__ float t[32][33];
    const int nb = blockIdx.x * 32, kb = blockIdx.y * 32;
    const int tx = threadIdx.x & 31, ty = threadIdx.x >> 5;
    #pragma unroll
    for (int i = 0; i < 32; i += 8)
        t[ty + i][tx] = W[(size_t)(kb + ty + i) * N + nb + tx];
    __syncthreads();
    #pragma unroll
    for (int i = 0; i < 32; i += 8)
        Wt[(size_t)(nb + ty + i) * K + kb + tx] = to_tf32(t[tx][ty + i]);
}

// ---------------------------------------------------------------------------
// WMMA tf32 GEMM: C[M,N] = A[M,K] @ Wt[N,K]^T + bias (+resid if EPI)
// Tile 128x128, BK=32, double-buffered cp.async, 8 warps (4 M x 2 N),
// warp tile 32x64 = 2x4 wmma m16n16k8 fragments, fp32 accumulation.
// ---------------------------------------------------------------------------
#define BM   128
#define BN   128
#define BK   32
#define BKP  40                          // padded K stride (160B, 16B-aligned)
#define ATILE_BYTES (128 * BKP * 4)      // 20480
#define STAGE_BYTES (2 * ATILE_BYTES)    // 40960
#define GEMM_SMEM   (2 * STAGE_BYTES)    // 81920 (epilogue reuses 64KB of it)

template <int EPI>
__global__ __launch_bounds__(256, 2)
void gemm_wmma(const float* __restrict__ A, const float* __restrict__ Wt,
               const float* __restrict__ bias, const float* __restrict__ resid,
               float* __restrict__ C, int N, int K) {
    extern __shared__ char smc[];
    const uint32_t sb = smem_u32(smc);
    const int tid = threadIdx.x;
    const int bm = blockIdx.y * BM;
    const int bn = blockIdx.x * BN;
    const int NS = K / BK;

    // global->shared load geometry: 8 threads per 32-float row
    const int lrow = tid >> 3;           // 0..31
    const int lc4  = (tid & 7) << 2;     // 0,4,...,28

    const int warp = tid >> 5;
    const int wm = warp & 3;             // M group (32 rows)
    const int wn = warp >> 2;            // N group (64 cols)

    wmma::fragment<wmma::accumulator, 16, 16, 8, float> acc[2][4];
    #pragma unroll
    for (int i = 0; i < 2; i++)
        #pragma unroll
        for (int j = 0; j < 4; j++) wmma::fill_fragment(acc[i][j], 0.0f);

#define LOAD_STAGE(buf, s) do {                                               \
    const size_t koff_ = (size_t)(s) * BK;                                    \
    _Pragma("unroll")                                                         \
    for (int j_ = 0; j_ < 4; ++j_) {                                          \
        cp16(sb + (buf) * STAGE_BYTES + ((lrow + 32 * j_) * BKP + lc4) * 4,   \
             A + (size_t)(bm + lrow + 32 * j_) * K + koff_ + lc4);            \
    }                                                                         \
    _Pragma("unroll")                                                         \
    for (int j_ = 0; j_ < 4; ++j_) {                                          \
        cp16(sb + (buf) * STAGE_BYTES + ATILE_BYTES +                         \
                 ((lrow + 32 * j_) * BKP + lc4) * 4,                          \
             Wt + (size_t)(bn + lrow + 32 * j_) * K + koff_ + lc4);           \
    }                                                                         \
    asm volatile("cp.async.commit_group;" ::: "memory");                      \
} while (0)

    LOAD_STAGE(0, 0);

    for (int s = 0; s < NS; ++s) {
        if (s + 1 < NS) {
            LOAD_STAGE((s + 1) & 1, s + 1);
            asm volatile("cp.async.wait_group 1;" ::: "memory");
        } else {
            asm volatile("cp.async.wait_group 0;" ::: "memory");
        }
        __syncthreads();

        const float* As = (const float*)(smc + (s & 1) * STAGE_BYTES);
        const float* Bs = (const float*)(smc + (s & 1) * STAGE_BYTES + ATILE_BYTES);

        #pragma unroll
        for (int kk = 0; kk < BK / 8; ++kk) {
            const int k0 = kk * 8;
            wmma::fragment<wmma::matrix_a, 16, 16, 8, wmma::precision::tf32,
                           wmma::row_major> af[2];
            #pragma unroll
            for (int i = 0; i < 2; i++) {
                wmma::load_matrix_sync(af[i],
                    As + (wm * 32 + i * 16) * BKP + k0, BKP);
                #pragma unroll
                for (int e = 0; e < af[i].num_elements; e++)
                    af[i].x[e] = to_tf32(af[i].x[e]);
            }
            wmma::fragment<wmma::matrix_b, 16, 16, 8, wmma::precision::tf32,
                           wmma::col_major> bf[4];
            #pragma unroll
            for (int j = 0; j < 4; j++)
                wmma::load_matrix_sync(bf[j],
                    Bs + (wn * 64 + j * 16) * BKP + k0, BKP);   // pre-rounded

            #pragma unroll
            for (int i = 0; i < 2; i++)
                #pragma unroll
                for (int j = 0; j < 4; j++)
                    wmma::mma_sync(acc[i][j], af[i], bf[j], acc[i][j]);
        }
        __syncthreads();
    }

    // epilogue: stage through smem (reuse tile buffers), coalesced writes
    float* esm = (float*)smc;            // 128x128 fp32 = 64KB
    #pragma unroll
    for (int i = 0; i < 2; i++)
        #pragma unroll
        for (int j = 0; j < 4; j++)
            wmma::store_matrix_sync(
                esm + (size_t)(wm * 32 + i * 16) * 128 + wn * 64 + j * 16,
                acc[i][j], 128, wmma::mem_row_major);
    __syncthreads();

    #pragma unroll
    for (int jj = 0; jj < 16; ++jj) {
        const int idx  = tid + 256 * jj;
        const int row  = idx >> 5;
        const int col4 = (idx & 31) << 2;
        float4 v = *(const float4*)(esm + row * 128 + col4);
        const float4 b4 = *(const float4*)(bias + bn + col4);
        v.x += b4.x; v.y += b4.y; v.z += b4.z; v.w += b4.w;
        if (EPI) {
            const float4 r4 = *(const float4*)(resid + (size_t)(bm + row) * N + bn + col4);
            v.x += r4.x; v.y += r4.y; v.z += r4.z; v.w += r4.w;
        }
        *(float4*)(C + (size_t)(bm + row) * N + bn + col4) = v;
    }
#undef LOAD_STAGE
}

// ---------------------------------------------------------------------------
// Flash-style causal attention with ALiBi (unchanged from R1).
// ---------------------------------------------------------------------------
#define QKV_STRIDE 132
#define P_STRIDE   68
#define ATTN_SMEM  ((3 * 64 * QKV_STRIDE + 64 * P_STRIDE) * 4)

__global__ __launch_bounds__(256)
void attn_kernel(const float* __restrict__ qkv, const float* __restrict__ alibi,
                 float* __restrict__ ctx) {
    extern __shared__ float sm[];
    float* Qs = sm;
    float* Ks = sm + 64 * QKV_STRIDE;
    float* Vs = sm + 2 * 64 * QKV_STRIDE;
    float* Ps = sm + 3 * 64 * QKV_STRIDE;

    const int tid = threadIdx.x;
    const int tx  = tid & 15;
    const int ty  = tid >> 4;
    const int qt  = blockIdx.x;
    const int bh  = blockIdx.y;
    const int b   = bh >> 4;
    const int h   = bh & 15;
    const int q0  = qt * 64;

    const size_t base = (size_t)b * SS * H3 + (size_t)h * (3 * HDD);

    #pragma unroll
    for (int t = 0; t < 8; t++) {
        int idx = tid + 256 * t;
        int r   = idx >> 5;
        int c4  = (idx & 31) << 2;
        float4 qv = *(const float4*)(qkv + base + (size_t)(q0 + r) * H3 + HDD + c4);
        qv.x *= ALPHA; qv.y *= ALPHA; qv.z *= ALPHA; qv.w *= ALPHA;
        *(float4*)(Qs + r * QKV_STRIDE + c4) = qv;
    }

    float m[4], l[4], o[4][8];
    #pragma unroll
    for (int r = 0; r < 4; r++) {
        m[r] = -INFINITY; l[r] = 0.0f;
        #pragma unroll
        for (int c = 0; c < 8; c++) o[r][c] = 0.0f;
    }

    const float* ali = alibi + (size_t)bh * SS;

    for (int kt = 0; kt <= qt; kt++) {
        const int k0 = kt * 64;
        __syncthreads();
        #pragma unroll
        for (int t = 0; t < 8; t++) {
            int idx = tid + 256 * t;
            int r   = idx >> 5;
            int c4  = (idx & 31) << 2;
            size_t g = base + (size_t)(k0 + r) * H3 + c4;
            *(float4*)(Ks + r * QKV_STRIDE + c4) = *(const float4*)(qkv + g);
            *(float4*)(Vs + r * QKV_STRIDE + c4) = *(const float4*)(qkv + g + 2 * HDD);
        }
        __syncthreads();

        float s[4][4];
        #pragma unroll
        for (int r = 0; r < 4; r++)
            #pragma unroll
            for (int c = 0; c < 4; c++) s[r][c] = 0.0f;

        #pragma unroll 4
        for (int kk = 0; kk < HDD; kk += 4) {
            float4 qv[4], kv[4];
            #pragma unroll
            for (int r = 0; r < 4; r++)
                qv[r] = *(const float4*)(Qs + (ty + 16 * r) * QKV_STRIDE + kk);
            #pragma unroll
            for (int c = 0; c < 4; c++)
                kv[c] = *(const float4*)(Ks + (tx + 16 * c) * QKV_STRIDE + kk);
            #pragma unroll
            for (int r = 0; r < 4; r++)
                #pragma unroll
                for (int c = 0; c < 4; c++)
                    s[r][c] += qv[r].x * kv[c].x + qv[r].y * kv[c].y +
                               qv[r].z * kv[c].z + qv[r].w * kv[c].w;
        }

        float av[4];
        #pragma unroll
        for (int c = 0; c < 4; c++) av[c] = ali[k0 + tx + 16 * c];
        const bool diag = (kt == qt);
        #pragma unroll
        for (int r = 0; r < 4; r++) {
            int ig = q0 + ty + 16 * r;
            #pragma unroll
            for (int c = 0; c < 4; c++) {
                int jg = k0 + tx + 16 * c;
                float val = s[r][c] + av[c];
                s[r][c] = (diag && (jg > ig)) ? -INFINITY : val;
            }
        }

        #pragma unroll
        for (int r = 0; r < 4; r++) {
            float mt = fmaxf(fmaxf(s[r][0], s[r][1]), fmaxf(s[r][2], s[r][3]));
            #pragma unroll
            for (int off = 8; off >= 1; off >>= 1)
                mt = fmaxf(mt, __shfl_xor_sync(0xffffffffu, mt, off, 16));
            float mn = fmaxf(m[r], mt);
            float f  = __expf(m[r] - mn);
            float ps = 0.0f;
            #pragma unroll
            for (int c = 0; c < 4; c++) {
                float p = __expf(s[r][c] - mn);
                s[r][c] = p;
                ps += p;
            }
            #pragma unroll
            for (int off = 8; off >= 1; off >>= 1)
                ps += __shfl_xor_sync(0xffffffffu, ps, off, 16);
            l[r] = l[r] * f + ps;
            m[r] = mn;
            #pragma unroll
            for (int c = 0; c < 8; c++) o[r][c] *= f;
            #pragma unroll
            for (int c = 0; c < 4; c++)
                Ps[(ty + 16 * r) * P_STRIDE + tx + 16 * c] = s[r][c];
        }
        __syncthreads();

        #pragma unroll 2
        for (int j = 0; j < 64; j++) {
            float pv[4], vv[8];
            #pragma unroll
            for (int r = 0; r < 4; r++) pv[r] = Ps[(ty + 16 * r) * P_STRIDE + j];
            #pragma unroll
            for (int c = 0; c < 8; c++) vv[c] = Vs[j * QKV_STRIDE + tx + 16 * c];
            #pragma unroll
            for (int r = 0; r < 4; r++)
                #pragma unroll
                for (int c = 0; c < 8; c++) o[r][c] += pv[r] * vv[c];
        }
    }

    #pragma unroll
    for (int r = 0; r < 4; r++) {
        float inv = 1.0f / l[r];
        int ig = q0 + ty + 16 * r;
        float* crow = ctx + ((size_t)b * SS + ig) * HH + h * HDD;
        #pragma unroll
        for (int c = 0; c < 8; c++) crow[tx + 16 * c] = o[r][c] * inv;
    }
}

// ---------------------------------------------------------------------------
// Launch
// ---------------------------------------------------------------------------
extern "C" void kernel_launch(void* const* d_in, const int* in_sizes, int n_in,
                              void* d_out, int out_size) {
    (void)in_sizes; (void)n_in; (void)out_size;
    const float* hs    = (const float*)d_in[0];
    const float* resid = (const float*)d_in[2];
    const float* alibi = (const float*)d_in[3];
    const float* Wqkv  = (const float*)d_in[4];
    const float* bqkv  = (const float*)d_in[5];
    const float* Wd    = (const float*)d_in[6];
    const float* bd    = (const float*)d_in[7];
    float* out = (float*)d_out;

    float *qkvp, *ctxp, *wqkvt, *wdt;
    cudaGetSymbolAddress((void**)&qkvp,  g_qkv);
    cudaGetSymbolAddress((void**)&ctxp,  g_ctx);
    cudaGetSymbolAddress((void**)&wqkvt, g_wqkvt);
    cudaGetSymbolAddress((void**)&wdt,   g_wdt);

    cudaFuncSetAttribute(gemm_wmma<0>, cudaFuncAttributeMaxDynamicSharedMemorySize, GEMM_SMEM);
    cudaFuncSetAttribute(gemm_wmma<1>, cudaFuncAttributeMaxDynamicSharedMemorySize, GEMM_SMEM);
    cudaFuncSetAttribute(attn_kernel,  cudaFuncAttributeMaxDynamicSharedMemorySize, ATTN_SMEM);

    // 0) transpose + tf32-round weights
    transpose_tf32<<<dim3(H3 / 32, HH / 32), 256>>>(Wqkv, wqkvt, HH, H3);
    transpose_tf32<<<dim3(HH / 32, HH / 32), 256>>>(Wd,   wdt,   HH, HH);

    // 1) qkv = hidden @ Wqkv + bqkv   (wmma tf32)
    gemm_wmma<0><<<dim3(H3 / BN, BSR / BM), 256, GEMM_SMEM>>>(
        hs, wqkvt, bqkv, nullptr, qkvp, H3, HH);

    // 2) attention
    attn_kernel<<<dim3(SS / 64, BB * NHH), 256, ATTN_SMEM>>>(qkvp, alibi, ctxp);

    // 3) out = ctx @ Wd + bd + residual   (wmma tf32)
    gemm_wmma<1><<<dim3(HH / BN, BSR / BM), 256, GEMM_SMEM>>>(
        ctxp, wdt, bd, resid, out, HH, HH);
}

// round 4
// speedup vs baseline: 1.6001x; 1.0681x over previous
#include <cuda_runtime.h>
#include <math.h>
#include <stdint.h>
#include <mma.h>

using namespace nvcuda;

// Problem constants
#define BB   2
#define SSQ  2048
#define HH   2048
#define NHH  16
#define HDD  128
#define H3   6144
#define BSR  4096
#define ALPHA 0.08838834764831845f

// Scratch
__device__ float g_qkv[(size_t)BSR * H3];
__device__ float g_ctx[(size_t)BSR * HH];
__device__ float g_wqkvt[(size_t)H3 * HH];
__device__ float g_wdt[(size_t)HH * HH];

// ---------------------------------------------------------------------------
// Helpers
// ---------------------------------------------------------------------------
__device__ __forceinline__ uint32_t smem_u32(const void* p) {
    uint32_t a;
    asm("{ .reg .u64 t; cvta.to.shared.u64 t, %1; cvt.u32.u64 %0, t; }" : "=r"(a) : "l"(p));
    return a;
}
__device__ __forceinline__ void cp16(uint32_t dst, const void* src) {
    asm volatile("cp.async.cg.shared.global [%0], [%1], 16;" :: "r"(dst), "l"(src));
}
__device__ __forceinline__ float to_tf32(float x) {
    uint32_t u;
    asm("cvt.rna.tf32.f32 %0, %1;" : "=r"(u) : "f"(x));
    return __uint_as_float(u);
}

// ---------------------------------------------------------------------------
// Transpose + round to tf32: Wt[n][k] = rna_tf32(W[k][n]).  W is [K][N].
// ---------------------------------------------------------------------------
__global__ __launch_bounds__(256)
void transpose_tf32(const float* __restrict__ W, float* __restrict__ Wt,
                    int K, int N) {
    __shared__ float t[32][33];
    const int nb = blockIdx.x * 32, kb = blockIdx.y * 32;
    const int tx = threadIdx.x & 31, ty = threadIdx.x >> 5;
    #pragma unroll
    for (int i = 0; i < 32; i += 8)
        t[ty + i][tx] = W[(size_t)(kb + ty + i) * N + nb + tx];
    __syncthreads();
    #pragma unroll
    for (int i = 0; i < 32; i += 8)
        Wt[(size_t)(nb + ty + i) * K + kb + tx] = to_tf32(t[tx][ty + i]);
}

// ---------------------------------------------------------------------------
// WMMA tf32 GEMM (unchanged from R3)
// ---------------------------------------------------------------------------
#define BM   128
#define BN   128
#define BK   32
#define BKP  40
#define ATILE_BYTES (128 * BKP * 4)
#define STAGE_BYTES (2 * ATILE_BYTES)
#define GEMM_SMEM   (2 * STAGE_BYTES)

template <int EPI>
__global__ __launch_bounds__(256, 2)
void gemm_wmma(const float* __restrict__ A, const float* __restrict__ Wt,
               const float* __restrict__ bias, const float* __restrict__ resid,
               float* __restrict__ C, int N, int K) {
    extern __shared__ char smc[];
    const uint32_t sb = smem_u32(smc);
    const int tid = threadIdx.x;
    const int bm = blockIdx.y * BM;
    const int bn = blockIdx.x * BN;
    const int NS = K / BK;

    const int lrow = tid >> 3;
    const int lc4  = (tid & 7) << 2;

    const int warp = tid >> 5;
    const int wm = warp & 3;
    const int wn = warp >> 2;

    wmma::fragment<wmma::accumulator, 16, 16, 8, float> acc[2][4];
    #pragma unroll
    for (int i = 0; i < 2; i++)
        #pragma unroll
        for (int j = 0; j < 4; j++) wmma::fill_fragment(acc[i][j], 0.0f);

#define LOAD_STAGE(buf, s) do {                                               \
    const size_t koff_ = (size_t)(s) * BK;                                    \
    _Pragma("unroll")                                                         \
    for (int j_ = 0; j_ < 4; ++j_) {                                          \
        cp16(sb + (buf) * STAGE_BYTES + ((lrow + 32 * j_) * BKP + lc4) * 4,   \
             A + (size_t)(bm + lrow + 32 * j_) * K + koff_ + lc4);            \
    }                                                                         \
    _Pragma("unroll")                                                         \
    for (int j_ = 0; j_ < 4; ++j_) {                                          \
        cp16(sb + (buf) * STAGE_BYTES + ATILE_BYTES +                         \
                 ((lrow + 32 * j_) * BKP + lc4) * 4,                          \
             Wt + (size_t)(bn + lrow + 32 * j_) * K + koff_ + lc4);           \
    }                                                                         \
    asm volatile("cp.async.commit_group;" ::: "memory");                      \
} while (0)

    LOAD_STAGE(0, 0);

    for (int s = 0; s < NS; ++s) {
        if (s + 1 < NS) {
            LOAD_STAGE((s + 1) & 1, s + 1);
            asm volatile("cp.async.wait_group 1;" ::: "memory");
        } else {
            asm volatile("cp.async.wait_group 0;" ::: "memory");
        }
        __syncthreads();

        const float* As = (const float*)(smc + (s & 1) * STAGE_BYTES);
        const float* Bs = (const float*)(smc + (s & 1) * STAGE_BYTES + ATILE_BYTES);

        #pragma unroll
        for (int kk = 0; kk < BK / 8; ++kk) {
            const int k0 = kk * 8;
            wmma::fragment<wmma::matrix_a, 16, 16, 8, wmma::precision::tf32,
                           wmma::row_major> af[2];
            #pragma unroll
            for (int i = 0; i < 2; i++) {
                wmma::load_matrix_sync(af[i],
                    As + (wm * 32 + i * 16) * BKP + k0, BKP);
                #pragma unroll
                for (int e = 0; e < af[i].num_elements; e++)
                    af[i].x[e] = to_tf32(af[i].x[e]);
            }
            wmma::fragment<wmma::matrix_b, 16, 16, 8, wmma::precision::tf32,
                           wmma::col_major> bf[4];
            #pragma unroll
            for (int j = 0; j < 4; j++)
                wmma::load_matrix_sync(bf[j],
                    Bs + (wn * 64 + j * 16) * BKP + k0, BKP);

            #pragma unroll
            for (int i = 0; i < 2; i++)
                #pragma unroll
                for (int j = 0; j < 4; j++)
                    wmma::mma_sync(acc[i][j], af[i], bf[j], acc[i][j]);
        }
        __syncthreads();
    }

    float* esm = (float*)smc;
    #pragma unroll
    for (int i = 0; i < 2; i++)
        #pragma unroll
        for (int j = 0; j < 4; j++)
            wmma::store_matrix_sync(
                esm + (size_t)(wm * 32 + i * 16) * 128 + wn * 64 + j * 16,
                acc[i][j], 128, wmma::mem_row_major);
    __syncthreads();

    #pragma unroll
    for (int jj = 0; jj < 16; ++jj) {
        const int idx  = tid + 256 * jj;
        const int row  = idx >> 5;
        const int col4 = (idx & 31) << 2;
        float4 v = *(const float4*)(esm + row * 128 + col4);
        const float4 b4 = *(const float4*)(bias + bn + col4);
        v.x += b4.x; v.y += b4.y; v.z += b4.z; v.w += b4.w;
        if (EPI) {
            const float4 r4 = *(const float4*)(resid + (size_t)(bm + row) * N + bn + col4);
            v.x += r4.x; v.y += r4.y; v.z += r4.z; v.w += r4.w;
        }
        *(float4*)(C + (size_t)(bm + row) * N + bn + col4) = v;
    }
#undef LOAD_STAGE
}

// ---------------------------------------------------------------------------
// WMMA tf32 flash attention with ALiBi.
// CTA = (64-row Q tile, bh). 256 threads / 8 warps.
// SMEM: Q,K,V,O [64][132] fp32 + S/P [64][68] fp32 = 152576 B.
// Per K-tile: S=Q@K^T (wmma) -> online softmax (4 thr/row) -> O+=P@V (wmma,
// O staged in SMEM so the rescale is a simple pass).
// ---------------------------------------------------------------------------
#define AQS 132
#define APS 68
#define ATTN_SMEM ((4 * 64 * AQS + 64 * APS) * 4)

__global__ __launch_bounds__(256, 1)
void attn_wmma(const float* __restrict__ qkv, const float* __restrict__ alibi,
               float* __restrict__ ctx) {
    extern __shared__ float sm[];
    float* Qs = sm;
    float* Ks = sm + 64 * AQS;
    float* Vs = sm + 2 * 64 * AQS;
    float* Os = sm + 3 * 64 * AQS;
    float* Ss = sm + 4 * 64 * AQS;

    const int tid  = threadIdx.x;
    const int warp = tid >> 5;
    const int qt = blockIdx.x;
    const int bh = blockIdx.y;
    const int b  = bh >> 4;
    const int h  = bh & 15;
    const int q0 = qt * 64;

    const size_t base = (size_t)b * SSQ * H3 + (size_t)h * (3 * HDD);

    // load Q (scaled by ALPHA, tf32-rounded), zero O
    #pragma unroll
    for (int t = 0; t < 8; t++) {
        int idx = tid + 256 * t;
        int r   = idx >> 5;
        int c4  = (idx & 31) << 2;
        float4 qv = *(const float4*)(qkv + base + (size_t)(q0 + r) * H3 + HDD + c4);
        qv.x = to_tf32(qv.x * ALPHA); qv.y = to_tf32(qv.y * ALPHA);
        qv.z = to_tf32(qv.z * ALPHA); qv.w = to_tf32(qv.w * ALPHA);
        *(float4*)(Qs + r * AQS + c4) = qv;
        *(float4*)(Os + r * AQS + c4) = make_float4(0.f, 0.f, 0.f, 0.f);
    }

    // softmax ownership: 4 threads per row
    const int r  = tid >> 2;       // 0..63
    const int qd = tid & 3;        // quad lane
    float mrow = -INFINITY, lrow = 0.0f;

    const float* alib = alibi + (size_t)bh * SSQ;

    for (int kt = 0; kt <= qt; kt++) {
        const int k0 = kt * 64;
        __syncthreads();   // prev PV reads done; Q stores visible (kt==0)

        // load K, V tiles (tf32-rounded)
        #pragma unroll
        for (int t = 0; t < 8; t++) {
            int idx = tid + 256 * t;
            int r2  = idx >> 5;
            int c4  = (idx & 31) << 2;
            size_t g = base + (size_t)(k0 + r2) * H3 + c4;
            float4 kv = *(const float4*)(qkv + g);
            kv.x = to_tf32(kv.x); kv.y = to_tf32(kv.y);
            kv.z = to_tf32(kv.z); kv.w = to_tf32(kv.w);
            *(float4*)(Ks + r2 * AQS + c4) = kv;
            float4 vv = *(const float4*)(qkv + g + 2 * HDD);
            vv.x = to_tf32(vv.x); vv.y = to_tf32(vv.y);
            vv.z = to_tf32(vv.z); vv.w = to_tf32(vv.w);
            *(float4*)(Vs + r2 * AQS + c4) = vv;
        }
        __syncthreads();

        // S = Q @ K^T : warp tile 16x32 (4 M-groups x 2 N-groups)
        {
            const int smr = (warp & 3) * 16;
            const int snc = (warp >> 2) * 32;
            wmma::fragment<wmma::accumulator, 16, 16, 8, float> sacc[2];
            wmma::fill_fragment(sacc[0], 0.0f);
            wmma::fill_fragment(sacc[1], 0.0f);
            #pragma unroll
            for (int ks = 0; ks < 16; ks++) {
                wmma::fragment<wmma::matrix_a, 16, 16, 8, wmma::precision::tf32,
                               wmma::row_major> af;
                wmma::load_matrix_sync(af, Qs + smr * AQS + ks * 8, AQS);
                #pragma unroll
                for (int j = 0; j < 2; j++) {
                    wmma::fragment<wmma::matrix_b, 16, 16, 8, wmma::precision::tf32,
                                   wmma::col_major> bf;
                    wmma::load_matrix_sync(bf, Ks + (snc + j * 16) * AQS + ks * 8, AQS);
                    wmma::mma_sync(sacc[j], af, bf, sacc[j]);
                }
            }
            wmma::store_matrix_sync(Ss + smr * APS + snc,      sacc[0], APS, wmma::mem_row_major);
            wmma::store_matrix_sync(Ss + smr * APS + snc + 16, sacc[1], APS, wmma::mem_row_major);
        }
        __syncthreads();

        // online softmax: thread (r, qd) owns cols qd*16..+15 of row r
        {
            const bool diag = (kt == qt);
            const int c0 = qd * 16;
            float sv[16];
            float mt = -INFINITY;
            #pragma unroll
            for (int c = 0; c < 16; c++) {
                float v = Ss[r * APS + c0 + c] + alib[k0 + c0 + c];
                if (diag && (c0 + c > r)) v = -INFINITY;   // k0 == q0 on diag
                sv[c] = v;
                mt = fmaxf(mt, v);
            }
            mt = fmaxf(mt, __shfl_xor_sync(0xffffffffu, mt, 1, 4));
            mt = fmaxf(mt, __shfl_xor_sync(0xffffffffu, mt, 2, 4));
            const float mn = fmaxf(mrow, mt);
            const float f  = __expf(mrow - mn);
            float ps = 0.0f;
            #pragma unroll
            for (int c = 0; c < 16; c++) {
                float p = __expf(sv[c] - mn);
                Ss[r * APS + c0 + c] = to_tf32(p);
                ps += p;
            }
            ps += __shfl_xor_sync(0xffffffffu, ps, 1, 4);
            ps += __shfl_xor_sync(0xffffffffu, ps, 2, 4);
            lrow = lrow * f + ps;
            mrow = mn;
            // rescale O row r, cols qd*32..+31
            float* orow = Os + r * AQS + qd * 32;
            #pragma unroll
            for (int j = 0; j < 32; j += 4) {
                float4 o = *(float4*)(orow + j);
                o.x *= f; o.y *= f; o.z *= f; o.w *= f;
                *(float4*)(orow + j) = o;
            }
        }
        __syncthreads();

        // O += P @ V : warp tile 16x64 (4 M-groups x 2 N-groups)
        {
            const int omr = (warp & 3) * 16;
            const int onc = (warp >> 2) * 64;
            wmma::fragment<wmma::accumulator, 16, 16, 8, float> oacc[4];
            #pragma unroll
            for (int j = 0; j < 4; j++)
                wmma::load_matrix_sync(oacc[j], Os + omr * AQS + onc + j * 16,
                                       AQS, wmma::mem_row_major);
            #pragma unroll
            for (int ks = 0; ks < 8; ks++) {
                wmma::fragment<wmma::matrix_a, 16, 16, 8, wmma::precision::tf32,
                               wmma::row_major> af;
                wmma::load_matrix_sync(af, Ss + omr * APS + ks * 8, APS);
                #pragma unroll
                for (int j = 0; j < 4; j++) {
                    wmma::fragment<wmma::matrix_b, 16, 16, 8, wmma::precision::tf32,
                                   wmma::row_major> bf;
                    wmma::load_matrix_sync(bf, Vs + ks * 8 * AQS + onc + j * 16, AQS);
                    wmma::mma_sync(oacc[j], af, bf, oacc[j]);
                }
            }
            #pragma unroll
            for (int j = 0; j < 4; j++)
                wmma::store_matrix_sync(Os + omr * AQS + onc + j * 16, oacc[j],
                                        AQS, wmma::mem_row_major);
        }
    }
    __syncthreads();

    // normalize + write ctx [B*S, H]
    {
        const float inv = 1.0f / lrow;
        float* crow = ctx + ((size_t)b * SSQ + q0 + r) * HH + h * HDD + qd * 32;
        const float* orow = Os + r * AQS + qd * 32;
        #pragma unroll
        for (int j = 0; j < 32; j += 4) {
            float4 o = *(const float4*)(orow + j);
            o.x *= inv; o.y *= inv; o.z *= inv; o.w *= inv;
            *(float4*)(crow + j) = o;
        }
    }
}

// ---------------------------------------------------------------------------
// Launch
// ---------------------------------------------------------------------------
extern "C" void kernel_launch(void* const* d_in, const int* in_sizes, int n_in,
                              void* d_out, int out_size) {
    (void)in_sizes; (void)n_in; (void)out_size;
    const float* hs    = (const float*)d_in[0];
    const float* resid = (const float*)d_in[2];
    const float* alibi = (const float*)d_in[3];
    const float* Wqkv  = (const float*)d_in[4];
    const float* bqkv  = (const float*)d_in[5];
    const float* Wd    = (const float*)d_in[6];
    const float* bd    = (const float*)d_in[7];
    float* out = (float*)d_out;

    float *qkvp, *ctxp, *wqkvt, *wdt;
    cudaGetSymbolAddress((void**)&qkvp,  g_qkv);
    cudaGetSymbolAddress((void**)&ctxp,  g_ctx);
    cudaGetSymbolAddress((void**)&wqkvt, g_wqkvt);
    cudaGetSymbolAddress((void**)&wdt,   g_wdt);

    cudaFuncSetAttribute(gemm_wmma<0>, cudaFuncAttributeMaxDynamicSharedMemorySize, GEMM_SMEM);
    cudaFuncSetAttribute(gemm_wmma<1>, cudaFuncAttributeMaxDynamicSharedMemorySize, GEMM_SMEM);
    cudaFuncSetAttribute(attn_wmma,    cudaFuncAttributeMaxDynamicSharedMemorySize, ATTN_SMEM);

    // 0) transpose + tf32-round weights
    transpose_tf32<<<dim3(H3 / 32, HH / 32), 256>>>(Wqkv, wqkvt, HH, H3);
    transpose_tf32<<<dim3(HH / 32, HH / 32), 256>>>(Wd,   wdt,   HH, HH);

    // 1) qkv = hidden @ Wqkv + bqkv
    gemm_wmma<0><<<dim3(H3 / BN, BSR / BM), 256, GEMM_SMEM>>>(
        hs, wqkvt, bqkv, nullptr, qkvp, H3, HH);

    // 2) attention (wmma tf32)
    attn_wmma<<<dim3(SSQ / 64, BB * NHH), 256, ATTN_SMEM>>>(qkvp, alibi, ctxp);

    // 3) out = ctx @ Wd + bd + residual
    gemm_wmma<1><<<dim3(HH / BN, BSR / BM), 256, GEMM_SMEM>>>(
        ctxp, wdt, bd, resid, out, HH, HH);
}

// round 5
// speedup vs baseline: 1.7022x; 1.0638x over previous
#include <cuda_runtime.h>
#include <math.h>
#include <stdint.h>
#include <mma.h>

using namespace nvcuda;

// Problem constants
#define BB   2
#define SSQ  2048
#define HH   2048
#define NHH  16
#define HDD  128
#define H3   6144
#define BSR  4096
#define ALPHA 0.08838834764831845f

// Scratch
__device__ float g_qkv[(size_t)BSR * H3];
__device__ float g_ctx[(size_t)BSR * HH];
__device__ float g_wqkvt[(size_t)H3 * HH];
__device__ float g_wdt[(size_t)HH * HH];

// ---------------------------------------------------------------------------
// Helpers
// ---------------------------------------------------------------------------
__device__ __forceinline__ uint32_t smem_u32(const void* p) {
    uint32_t a;
    asm("{ .reg .u64 t; cvta.to.shared.u64 t, %1; cvt.u32.u64 %0, t; }" : "=r"(a) : "l"(p));
    return a;
}
__device__ __forceinline__ void cp16(uint32_t dst, const void* src) {
    asm volatile("cp.async.cg.shared.global [%0], [%1], 16;" :: "r"(dst), "l"(src));
}
__device__ __forceinline__ float to_tf32(float x) {
    uint32_t u;
    asm("cvt.rna.tf32.f32 %0, %1;" : "=r"(u) : "f"(x));
    return __uint_as_float(u);
}

// ---------------------------------------------------------------------------
// Transpose + round to tf32: Wt[n][k] = rna_tf32(W[k][n]).  W is [K][N].
// ---------------------------------------------------------------------------
__global__ __launch_bounds__(256)
void transpose_tf32(const float* __restrict__ W, float* __restrict__ Wt,
                    int K, int N) {
    __shared__ float t[32][33];
    const int nb = blockIdx.x * 32, kb = blockIdx.y * 32;
    const int tx = threadIdx.x & 31, ty = threadIdx.x >> 5;
    #pragma unroll
    for (int i = 0; i < 32; i += 8)
        t[ty + i][tx] = W[(size_t)(kb + ty + i) * N + nb + tx];
    __syncthreads();
    #pragma unroll
    for (int i = 0; i < 32; i += 8)
        Wt[(size_t)(nb + ty + i) * K + kb + tx] = to_tf32(t[tx][ty + i]);
}

// ---------------------------------------------------------------------------
// WMMA tf32 GEMM (unchanged)
// ---------------------------------------------------------------------------
#define BM   128
#define BN   128
#define BK   32
#define BKP  40
#define ATILE_BYTES (128 * BKP * 4)
#define STAGE_BYTES (2 * ATILE_BYTES)
#define GEMM_SMEM   (2 * STAGE_BYTES)

template <int EPI>
__global__ __launch_bounds__(256, 2)
void gemm_wmma(const float* __restrict__ A, const float* __restrict__ Wt,
               const float* __restrict__ bias, const float* __restrict__ resid,
               float* __restrict__ C, int N, int K) {
    extern __shared__ char smc[];
    const uint32_t sb = smem_u32(smc);
    const int tid = threadIdx.x;
    const int bm = blockIdx.y * BM;
    const int bn = blockIdx.x * BN;
    const int NS = K / BK;

    const int lrow = tid >> 3;
    const int lc4  = (tid & 7) << 2;

    const int warp = tid >> 5;
    const int wm = warp & 3;
    const int wn = warp >> 2;

    wmma::fragment<wmma::accumulator, 16, 16, 8, float> acc[2][4];
    #pragma unroll
    for (int i = 0; i < 2; i++)
        #pragma unroll
        for (int j = 0; j < 4; j++) wmma::fill_fragment(acc[i][j], 0.0f);

#define LOAD_STAGE(buf, s) do {                                               \
    const size_t koff_ = (size_t)(s) * BK;                                    \
    _Pragma("unroll")                                                         \
    for (int j_ = 0; j_ < 4; ++j_) {                                          \
        cp16(sb + (buf) * STAGE_BYTES + ((lrow + 32 * j_) * BKP + lc4) * 4,   \
             A + (size_t)(bm + lrow + 32 * j_) * K + koff_ + lc4);            \
    }                                                                         \
    _Pragma("unroll")                                                         \
    for (int j_ = 0; j_ < 4; ++j_) {                                          \
        cp16(sb + (buf) * STAGE_BYTES + ATILE_BYTES +                         \
                 ((lrow + 32 * j_) * BKP + lc4) * 4,                          \
             Wt + (size_t)(bn + lrow + 32 * j_) * K + koff_ + lc4);           \
    }                                                                         \
    asm volatile("cp.async.commit_group;" ::: "memory");                      \
} while (0)

    LOAD_STAGE(0, 0);

    for (int s = 0; s < NS; ++s) {
        if (s + 1 < NS) {
            LOAD_STAGE((s + 1) & 1, s + 1);
            asm volatile("cp.async.wait_group 1;" ::: "memory");
        } else {
            asm volatile("cp.async.wait_group 0;" ::: "memory");
        }
        __syncthreads();

        const float* As = (const float*)(smc + (s & 1) * STAGE_BYTES);
        const float* Bs = (const float*)(smc + (s & 1) * STAGE_BYTES + ATILE_BYTES);

        #pragma unroll
        for (int kk = 0; kk < BK / 8; ++kk) {
            const int k0 = kk * 8;
            wmma::fragment<wmma::matrix_a, 16, 16, 8, wmma::precision::tf32,
                           wmma::row_major> af[2];
            #pragma unroll
            for (int i = 0; i < 2; i++) {
                wmma::load_matrix_sync(af[i],
                    As + (wm * 32 + i * 16) * BKP + k0, BKP);
                #pragma unroll
                for (int e = 0; e < af[i].num_elements; e++)
                    af[i].x[e] = to_tf32(af[i].x[e]);
            }
            wmma::fragment<wmma::matrix_b, 16, 16, 8, wmma::precision::tf32,
                           wmma::col_major> bf[4];
            #pragma unroll
            for (int j = 0; j < 4; j++)
                wmma::load_matrix_sync(bf[j],
                    Bs + (wn * 64 + j * 16) * BKP + k0, BKP);

            #pragma unroll
            for (int i = 0; i < 2; i++)
                #pragma unroll
                for (int j = 0; j < 4; j++)
                    wmma::mma_sync(acc[i][j], af[i], bf[j], acc[i][j]);
        }
        __syncthreads();
    }

    float* esm = (float*)smc;
    #pragma unroll
    for (int i = 0; i < 2; i++)
        #pragma unroll
        for (int j = 0; j < 4; j++)
            wmma::store_matrix_sync(
                esm + (size_t)(wm * 32 + i * 16) * 128 + wn * 64 + j * 16,
                acc[i][j], 128, wmma::mem_row_major);
    __syncthreads();

    #pragma unroll
    for (int jj = 0; jj < 16; ++jj) {
        const int idx  = tid + 256 * jj;
        const int row  = idx >> 5;
        const int col4 = (idx & 31) << 2;
        float4 v = *(const float4*)(esm + row * 128 + col4);
        const float4 b4 = *(const float4*)(bias + bn + col4);
        v.x += b4.x; v.y += b4.y; v.z += b4.z; v.w += b4.w;
        if (EPI) {
            const float4 r4 = *(const float4*)(resid + (size_t)(bm + row) * N + bn + col4);
            v.x += r4.x; v.y += r4.y; v.z += r4.z; v.w += r4.w;
        }
        *(float4*)(C + (size_t)(bm + row) * N + bn + col4) = v;
    }
#undef LOAD_STAGE
}

// ---------------------------------------------------------------------------
// WMMA tf32 flash attention with ALiBi — O resident in accumulator registers.
// CTA = (64-row Q tile, bh). 256 threads / 8 warps.
// SMEM: Q,K,V [64][132] + S/P [64][68] + fRow[64]  = 119040 B.
// Accumulator row mapping discovered at runtime via an index-fill fragment.
// ---------------------------------------------------------------------------
#define AQS 132
#define APS 68
#define ATTN_SMEM ((3 * 64 * AQS + 64 * APS + 64) * 4)

__global__ __launch_bounds__(256, 1)
void attn_wmma(const float* __restrict__ qkv, const float* __restrict__ alibi,
               float* __restrict__ ctx) {
    extern __shared__ float sm[];
    float* Qs   = sm;
    float* Ks   = sm + 64 * AQS;
    float* Vs   = sm + 2 * 64 * AQS;
    float* Ss   = sm + 3 * 64 * AQS;
    float* fRow = sm + 3 * 64 * AQS + 64 * APS;

    const int tid  = threadIdx.x;
    const int warp = tid >> 5;
    const int qt = blockIdx.x;
    const int bh = blockIdx.y;
    const int b  = bh >> 4;
    const int h  = bh & 15;
    const int q0 = qt * 64;

    const size_t base = (size_t)b * SSQ * H3 + (size_t)h * (3 * HDD);

    // --- discover accumulator lane->row mapping (once) ---
    if (tid < 256) {
        const int rr = tid >> 4, cc = tid & 15;
        Ss[rr * APS + cc] = (float)rr;
    }
    __syncthreads();
    int rid[8];
    {
        wmma::fragment<wmma::accumulator, 16, 16, 8, float> rmap;
        wmma::load_matrix_sync(rmap, Ss, APS, wmma::mem_row_major);
        #pragma unroll
        for (int e = 0; e < 8; e++) rid[e] = (int)rmap.x[e];
    }
    __syncthreads();

    // load Q tile (scaled by ALPHA, tf32-rounded)
    #pragma unroll
    for (int t = 0; t < 8; t++) {
        int idx = tid + 256 * t;
        int r2  = idx >> 5;
        int c4  = (idx & 31) << 2;
        float4 qv = *(const float4*)(qkv + base + (size_t)(q0 + r2) * H3 + HDD + c4);
        qv.x = to_tf32(qv.x * ALPHA); qv.y = to_tf32(qv.y * ALPHA);
        qv.z = to_tf32(qv.z * ALPHA); qv.w = to_tf32(qv.w * ALPHA);
        *(float4*)(Qs + r2 * AQS + c4) = qv;
    }

    // O accumulators: warp tile 16 rows x 64 cols, resident all loop
    const int omr = (warp & 3) * 16;
    const int onc = (warp >> 2) * 64;
    wmma::fragment<wmma::accumulator, 16, 16, 8, float> oacc[4];
    #pragma unroll
    for (int j = 0; j < 4; j++) wmma::fill_fragment(oacc[j], 0.0f);

    // softmax ownership: 4 threads per row
    const int r  = tid >> 2;
    const int qd = tid & 3;
    float mrow = -INFINITY, lrow = 0.0f;

    const float* alib = alibi + (size_t)bh * SSQ;

    for (int kt = 0; kt <= qt; kt++) {
        const int k0 = kt * 64;
        __syncthreads();   // prior-tile Ss/Vs reads done; Q stores visible (kt==0)

        // load K, V tiles (tf32-rounded)
        #pragma unroll
        for (int t = 0; t < 8; t++) {
            int idx = tid + 256 * t;
            int r2  = idx >> 5;
            int c4  = (idx & 31) << 2;
            size_t g = base + (size_t)(k0 + r2) * H3 + c4;
            float4 kv = *(const float4*)(qkv + g);
            kv.x = to_tf32(kv.x); kv.y = to_tf32(kv.y);
            kv.z = to_tf32(kv.z); kv.w = to_tf32(kv.w);
            *(float4*)(Ks + r2 * AQS + c4) = kv;
            float4 vv = *(const float4*)(qkv + g + 2 * HDD);
            vv.x = to_tf32(vv.x); vv.y = to_tf32(vv.y);
            vv.z = to_tf32(vv.z); vv.w = to_tf32(vv.w);
            *(float4*)(Vs + r2 * AQS + c4) = vv;
        }
        __syncthreads();

        // S = Q @ K^T : warp tile 16x32
        {
            const int snc = (warp >> 2) * 32;
            wmma::fragment<wmma::accumulator, 16, 16, 8, float> sacc[2];
            wmma::fill_fragment(sacc[0], 0.0f);
            wmma::fill_fragment(sacc[1], 0.0f);
            #pragma unroll
            for (int ks = 0; ks < 16; ks++) {
                wmma::fragment<wmma::matrix_a, 16, 16, 8, wmma::precision::tf32,
                               wmma::row_major> af;
                wmma::load_matrix_sync(af, Qs + omr * AQS + ks * 8, AQS);
                #pragma unroll
                for (int j = 0; j < 2; j++) {
                    wmma::fragment<wmma::matrix_b, 16, 16, 8, wmma::precision::tf32,
                                   wmma::col_major> bf;
                    wmma::load_matrix_sync(bf, Ks + (snc + j * 16) * AQS + ks * 8, AQS);
                    wmma::mma_sync(sacc[j], af, bf, sacc[j]);
                }
            }
            wmma::store_matrix_sync(Ss + omr * APS + snc,      sacc[0], APS, wmma::mem_row_major);
            wmma::store_matrix_sync(Ss + omr * APS + snc + 16, sacc[1], APS, wmma::mem_row_major);
        }
        __syncthreads();

        // online softmax: thread (r, qd) owns cols qd*16..+15 of row r
        {
            const bool diag = (kt == qt);
            const int c0 = qd * 16;
            float sv[16];
            float mt = -INFINITY;
            #pragma unroll
            for (int c = 0; c < 16; c++) {
                float v = Ss[r * APS + c0 + c] + alib[k0 + c0 + c];
                if (diag && (c0 + c > r)) v = -INFINITY;
                sv[c] = v;
                mt = fmaxf(mt, v);
            }
            mt = fmaxf(mt, __shfl_xor_sync(0xffffffffu, mt, 1, 4));
            mt = fmaxf(mt, __shfl_xor_sync(0xffffffffu, mt, 2, 4));
            const float mn = fmaxf(mrow, mt);
            const float f  = __expf(mrow - mn);
            float ps = 0.0f;
            #pragma unroll
            for (int c = 0; c < 16; c++) {
                float p = __expf(sv[c] - mn);
                Ss[r * APS + c0 + c] = to_tf32(p);
                ps += p;
            }
            ps += __shfl_xor_sync(0xffffffffu, ps, 1, 4);
            ps += __shfl_xor_sync(0xffffffffu, ps, 2, 4);
            lrow = lrow * f + ps;
            mrow = mn;
            if (qd == 0) fRow[r] = f;
        }
        __syncthreads();

        // rescale O in registers, then O += P @ V
        {
            float fr[8];
            #pragma unroll
            for (int e = 0; e < 8; e++) fr[e] = fRow[omr + rid[e]];
            #pragma unroll
            for (int j = 0; j < 4; j++)
                #pragma unroll
                for (int e = 0; e < 8; e++) oacc[j].x[e] *= fr[e];

            #pragma unroll
            for (int ks = 0; ks < 8; ks++) {
                wmma::fragment<wmma::matrix_a, 16, 16, 8, wmma::precision::tf32,
                               wmma::row_major> af;
                wmma::load_matrix_sync(af, Ss + omr * APS + ks * 8, APS);
                #pragma unroll
                for (int j = 0; j < 4; j++) {
                    wmma::fragment<wmma::matrix_b, 16, 16, 8, wmma::precision::tf32,
                                   wmma::row_major> bf;
                    wmma::load_matrix_sync(bf, Vs + ks * 8 * AQS + onc + j * 16, AQS);
                    wmma::mma_sync(oacc[j], af, bf, oacc[j]);
                }
            }
        }
    }

    // spill O to SMEM once (reuse K buffer), normalize, write ctx
    __syncthreads();
    #pragma unroll
    for (int j = 0; j < 4; j++)
        wmma::store_matrix_sync(Ks + omr * AQS + onc + j * 16, oacc[j],
                                AQS, wmma::mem_row_major);
    __syncthreads();
    {
        const float inv = 1.0f / lrow;
        float* crow = ctx + ((size_t)b * SSQ + q0 + r) * HH + h * HDD + qd * 32;
        const float* orow = Ks + r * AQS + qd * 32;
        #pragma unroll
        for (int j = 0; j < 32; j += 4) {
            float4 o = *(const float4*)(orow + j);
            o.x *= inv; o.y *= inv; o.z *= inv; o.w *= inv;
            *(float4*)(crow + j) = o;
        }
    }
}

// ---------------------------------------------------------------------------
// Launch
// ---------------------------------------------------------------------------
extern "C" void kernel_launch(void* const* d_in, const int* in_sizes, int n_in,
                              void* d_out, int out_size) {
    (void)in_sizes; (void)n_in; (void)out_size;
    const float* hs    = (const float*)d_in[0];
    const float* resid = (const float*)d_in[2];
    const float* alibi = (const float*)d_in[3];
    const float* Wqkv  = (const float*)d_in[4];
    const float* bqkv  = (const float*)d_in[5];
    const float* Wd    = (const float*)d_in[6];
    const float* bd    = (const float*)d_in[7];
    float* out = (float*)d_out;

    float *qkvp, *ctxp, *wqkvt, *wdt;
    cudaGetSymbolAddress((void**)&qkvp,  g_qkv);
    cudaGetSymbolAddress((void**)&ctxp,  g_ctx);
    cudaGetSymbolAddress((void**)&wqkvt, g_wqkvt);
    cudaGetSymbolAddress((void**)&wdt,   g_wdt);

    cudaFuncSetAttribute(gemm_wmma<0>, cudaFuncAttributeMaxDynamicSharedMemorySize, GEMM_SMEM);
    cudaFuncSetAttribute(gemm_wmma<1>, cudaFuncAttributeMaxDynamicSharedMemorySize, GEMM_SMEM);
    cudaFuncSetAttribute(attn_wmma,    cudaFuncAttributeMaxDynamicSharedMemorySize, ATTN_SMEM);

    // 0) transpose + tf32-round weights
    transpose_tf32<<<dim3(H3 / 32, HH / 32), 256>>>(Wqkv, wqkvt, HH, H3);
    transpose_tf32<<<dim3(HH / 32, HH / 32), 256>>>(Wd,   wdt,   HH, HH);

    // 1) qkv = hidden @ Wqkv + bqkv
    gemm_wmma<0><<<dim3(H3 / BN, BSR / BM), 256, GEMM_SMEM>>>(
        hs, wqkvt, bqkv, nullptr, qkvp, H3, HH);

    // 2) attention (wmma tf32, register-resident O)
    attn_wmma<<<dim3(SSQ / 64, BB * NHH), 256, ATTN_SMEM>>>(qkvp, alibi, ctxp);

    // 3) out = ctx @ Wd + bd + residual
    gemm_wmma<1><<<dim3(HH / BN, BSR / BM), 256, GEMM_SMEM>>>(
        ctxp, wdt, bd, resid, out, HH, HH);
}